// round 10
// baseline (speedup 1.0000x reference)
#include <cuda_runtime.h>
#include <cstdint>

#define Bv 4
#define Sv 4096
#define Hv 32
#define Dv 64
#define NSTEPS 128
#define ROWSTRIDE (Hv * Dv)       // 2048 floats between consecutive s
#define THREADS 512
#define WARPS 16
#define CHROWS 64                 // rows per chunk (one CTA)
#define CHUNKS (Sv / CHROWS)      // 64 chunks per (b,h)
#define NBH (Bv * Hv)             // 128
#define FULL 0xffffffffu

// cross-CTA inclusive prefix of kn-cumsum (device globals: no allocation)
__device__ __align__(16) float g_pref[NBH][CHUNKS][64];
__device__ int g_flag[NBH][CHUNKS];

__global__ void reset_flags_kernel() {
    int i = blockIdx.x * blockDim.x + threadIdx.x;
    if (i < NBH * CHUNKS) ((int*)g_flag)[i] = 0;
}

// sum across the 8 lanes of a row-group (lanes g*8..g*8+7)
__device__ __forceinline__ float grp8_sum(float v) {
    v += __shfl_xor_sync(FULL, v, 4);
    v += __shfl_xor_sync(FULL, v, 2);
    v += __shfl_xor_sync(FULL, v, 1);
    return v;
}
// inclusive scan across the 4 row-groups (stride-8 lanes)
__device__ __forceinline__ float scan_grp(float v, int lane) {
    float t = __shfl_up_sync(FULL, v, 8);
    if (lane >= 8) v += t;
    t = __shfl_up_sync(FULL, v, 16);
    if (lane >= 16) v += t;
    return v;
}
__device__ __forceinline__ float4 relu4(float4 a) {
    return make_float4(fmaxf(a.x, 0.f), fmaxf(a.y, 0.f),
                       fmaxf(a.z, 0.f), fmaxf(a.w, 0.f));
}
__device__ __forceinline__ float dot4(float4 a, float4 b) {
    return fmaf(a.x, b.x, fmaf(a.y, b.y, fmaf(a.z, b.z, a.w * b.w)));
}
__device__ __forceinline__ void cp16(float* dst_smem, const float* src) {
    uint32_t d = (uint32_t)__cvta_generic_to_shared(dst_smem);
    asm volatile("cp.async.cg.shared.global [%0], [%1], 16;"
                 :: "r"(d), "l"(src) : "memory");
}

__global__ __launch_bounds__(THREADS, 2)
void rope_ctx_kernel(const float* __restrict__ q,
                     const float* __restrict__ k,
                     const float* __restrict__ cos_step,
                     const float* __restrict__ sin_step,
                     float* __restrict__ out)
{
    __shared__ float  s_k[CHROWS * 64];      // 16 KB
    __shared__ float  s_q[CHROWS * 64];      // 16 KB
    __shared__ float2 s_tab[NSTEPS];
    __shared__ float  s_agg[64][18];
    __shared__ float  s_pref[64][18];        // [d][w+1] incl; [d][0]=0; tot [16]
    __shared__ __align__(16) float s_base[64];

    const int tid  = threadIdx.x;
    const int w    = tid >> 5;               // 0..15
    const int lane = tid & 31;
    const int g    = lane >> 3;              // row group 0..3
    const int j    = lane & 7;               // dim slot within row
    const int bh   = blockIdx.x & (NBH - 1); // stride mapping: c spreads waves
    const int c    = blockIdx.x >> 7;
    const int b    = bh >> 5;                // H = 32
    const int h    = bh & 31;

    const int dx = 4 * j;             // x dims: dx..dx+3 ; y dims: 32+dx..
    const int dy = 32 + 4 * j;
    const int r  = (w << 2) + g;      // this thread's row within the chunk
    const int sodx = (r << 6) + dx;
    const int sody = (r << 6) + dy;

    const size_t base = (size_t)b * Sv * ROWSTRIDE + (size_t)h * Dv
                      + (size_t)c * CHROWS * ROWSTRIDE;
    const float* kp = k + base + (size_t)r * ROWSTRIDE;
    const float* qp = q + base + (size_t)r * ROWSTRIDE;
    const size_t KOUT = (size_t)Bv * Sv * ROWSTRIDE;

    // ---- stage this thread's own row slots (per-thread-exact; no barrier) --
    cp16(s_k + sodx, kp + dx);
    cp16(s_k + sody, kp + dy);
    cp16(s_q + sodx, qp + dx);
    cp16(s_q + sody, qp + dy);
    asm volatile("cp.async.commit_group;" ::: "memory");

    if (tid < NSTEPS) {
        s_tab[tid] = make_float2(cos_step[tid * Dv], sin_step[tid * Dv]);
    }

    asm volatile("cp.async.wait_group 0;" ::: "memory");

    float4 kx = *(const float4*)(s_k + sodx);
    float4 ky = *(const float4*)(s_k + sody);
    float4 qx = *(const float4*)(s_q + sodx);
    float4 qy = *(const float4*)(s_q + sody);

    // ---- k: relu + norm (one 3-shfl reduction serves all 4 rows) ----------
    float4 knx = relu4(kx), kny = relu4(ky);
    float ss = grp8_sum(dot4(knx, knx) + dot4(kny, kny));
    float kinv = __fdividef(1.f, sqrtf(ss) + 1e-6f);
    knx.x *= kinv; knx.y *= kinv; knx.z *= kinv; knx.w *= kinv;
    kny.x *= kinv; kny.y *= kinv; kny.z *= kinv; kny.w *= kinv;

    // ---- in-warp inclusive scan across the 4 rows, per component ----------
    float4 ix, iy;
    ix.x = scan_grp(knx.x, lane); ix.y = scan_grp(knx.y, lane);
    ix.z = scan_grp(knx.z, lane); ix.w = scan_grp(knx.w, lane);
    iy.x = scan_grp(kny.x, lane); iy.y = scan_grp(kny.y, lane);
    iy.z = scan_grp(kny.z, lane); iy.w = scan_grp(kny.w, lane);

    if (g == 3) {                     // group 3 holds the warp's 4-row totals
        s_agg[dx    ][w] = ix.x; s_agg[dx + 1][w] = ix.y;
        s_agg[dx + 2][w] = ix.z; s_agg[dx + 3][w] = ix.w;
        s_agg[dy    ][w] = iy.x; s_agg[dy + 1][w] = iy.y;
        s_agg[dy + 2][w] = iy.z; s_agg[dy + 3][w] = iy.w;
    }

    // ---- q: relu + norm (independent; overlaps barrier arrival) -----------
    float4 qrx = relu4(qx), qry = relu4(qy);
    float qs = grp8_sum(dot4(qrx, qrx) + dot4(qry, qry));
    float qinv = __fdividef(1.f, sqrtf(qs) + 1e-6f);

    __syncthreads();                  // B1: s_agg published

    // ---- cross-warp scan: warp w scans dims 4w..4w+3 over 16 entries ------
    #pragma unroll
    for (int dd = 0; dd < 4; ++dd) {
        const int d = 4 * w + dd;
        float v = (lane < WARPS) ? s_agg[d][lane] : 0.f;
        float u;
        u = __shfl_up_sync(FULL, v, 1);  if (lane >= 1) v += u;
        u = __shfl_up_sync(FULL, v, 2);  if (lane >= 2) v += u;
        u = __shfl_up_sync(FULL, v, 4);  if (lane >= 4) v += u;
        u = __shfl_up_sync(FULL, v, 8);  if (lane >= 8) v += u;
        if (lane < WARPS) s_pref[d][lane + 1] = v;   // excl at [w], total [16]
        if (lane == 0) s_pref[d][0] = 0.f;
    }
    __syncthreads();                  // B2: s_pref + chunk totals ready

    // ---- prefix chain (warp 0 only): spin, read base, publish, flag -------
    if (w == 0) {
        if (lane == 0 && c > 0) {
            volatile int* f = &g_flag[bh][c - 1];
            while (*f == 0) { __nanosleep(32); }
        }
        __syncwarp();
        if (lane < 16) {
            const int d = 4 * lane;
            float4 b4 = make_float4(0.f, 0.f, 0.f, 0.f);
            if (c > 0) b4 = __ldcg((const float4*)&g_pref[bh][c - 1][d]);
            float4 p4;
            p4.x = b4.x + s_pref[d    ][WARPS];
            p4.y = b4.y + s_pref[d + 1][WARPS];
            p4.z = b4.z + s_pref[d + 2][WARPS];
            p4.w = b4.w + s_pref[d + 3][WARPS];
            *(float4*)&g_pref[bh][c][d] = p4;   // inclusive prefix for successor
            *(float4*)&s_base[d] = b4;          // exclusive base for this CTA
        }
        __threadfence();
        __syncwarp();
        if (lane == 0) atomicExch(&g_flag[bh][c], 1);
    }
    __syncthreads();                  // B3: s_base ready

    // ---- assemble inclusive cum, dot, position, rope, store ----------------
    float4 basex = *(const float4*)&s_base[dx];
    float4 basey = *(const float4*)&s_base[dy];

    float4 cx, cy;
    cx.x = basex.x + s_pref[dx    ][w] + ix.x;
    cx.y = basex.y + s_pref[dx + 1][w] + ix.y;
    cx.z = basex.z + s_pref[dx + 2][w] + ix.z;
    cx.w = basex.w + s_pref[dx + 3][w] + ix.w;
    cy.x = basey.x + s_pref[dy    ][w] + iy.x;
    cy.y = basey.y + s_pref[dy + 1][w] + iy.y;
    cy.z = basey.z + s_pref[dy + 2][w] + iy.z;
    cy.w = basey.w + s_pref[dy + 3][w] + iy.w;

    float dot = grp8_sum(dot4(qrx, cx) + dot4(qry, cy)) * qinv;

    float pp = fminf(fmaxf(dot * (1.f / 32.f), 0.f), 127.f);
    float pf = floorf(pp);
    int   fi = (int)pf;
    int   ci = (int)ceilf(pp);
    float fr = pp - pf;
    float2 t0 = s_tab[fi], t1 = s_tab[ci];
    float cn = fmaf(fr, t1.x - t0.x, t0.x);
    float sn = fmaf(fr, t1.y - t0.y, t0.y);

    float4 oqx, oqy, okx, oky;
    oqx.x = fmaf(qx.x, cn, -qy.x * sn);  oqy.x = fmaf(qy.x, cn, qx.x * sn);
    oqx.y = fmaf(qx.y, cn, -qy.y * sn);  oqy.y = fmaf(qy.y, cn, qx.y * sn);
    oqx.z = fmaf(qx.z, cn, -qy.z * sn);  oqy.z = fmaf(qy.z, cn, qx.z * sn);
    oqx.w = fmaf(qx.w, cn, -qy.w * sn);  oqy.w = fmaf(qy.w, cn, qx.w * sn);
    okx.x = fmaf(kx.x, cn, -ky.x * sn);  oky.x = fmaf(ky.x, cn, kx.x * sn);
    okx.y = fmaf(kx.y, cn, -ky.y * sn);  oky.y = fmaf(ky.y, cn, kx.y * sn);
    okx.z = fmaf(kx.z, cn, -ky.z * sn);  oky.z = fmaf(ky.z, cn, kx.z * sn);
    okx.w = fmaf(kx.w, cn, -ky.w * sn);  oky.w = fmaf(ky.w, cn, kx.w * sn);

    float* og = out + base + (size_t)r * ROWSTRIDE;
    *(float4*)(og + dx)             = oqx;
    *(float4*)(og + dy)             = oqy;
    *(float4*)(og + KOUT + dx)      = okx;
    *(float4*)(og + KOUT + dy)      = oky;
}

extern "C" void kernel_launch(void* const* d_in, const int* in_sizes, int n_in,
                              void* d_out, int out_size)
{
    const float* q        = (const float*)d_in[0];
    const float* k        = (const float*)d_in[1];
    // d_in[2] = v (unused by the reference math)
    const float* cos_step = (const float*)d_in[3];
    const float* sin_step = (const float*)d_in[4];
    // d_in[5] = offset (unused by the reference math)

    reset_flags_kernel<<<8, 1024>>>();
    rope_ctx_kernel<<<NBH * CHUNKS, THREADS>>>(q, k, cos_step, sin_step,
                                               (float*)d_out);
}

// round 11
// speedup vs baseline: 1.6916x; 1.6916x over previous
#include <cuda_runtime.h>
#include <cstdint>

#define Bv 4
#define Sv 4096
#define Hv 32
#define Dv 64
#define NSTEPS 128
#define ROWSTRIDE (Hv * Dv)       // 2048 floats between consecutive s
#define TILE 128                  // rows per tile (4 per warp)
#define NTILES (Sv / TILE)        // 32
#define TILE_FLOATS (TILE * Dv)   // 8192 floats = 32 KB
#define FULL 0xffffffffu

// sum across the 8 lanes of a row-group (lanes g*8..g*8+7)
__device__ __forceinline__ float grp8_sum(float v) {
    v += __shfl_xor_sync(FULL, v, 4);
    v += __shfl_xor_sync(FULL, v, 2);
    v += __shfl_xor_sync(FULL, v, 1);
    return v;
}

// inclusive scan across the 4 row-groups (stride-8 lanes)
__device__ __forceinline__ float scan_grp(float v, int lane) {
    float t = __shfl_up_sync(FULL, v, 8);
    if (lane >= 8) v += t;
    t = __shfl_up_sync(FULL, v, 16);
    if (lane >= 16) v += t;
    return v;
}

__device__ __forceinline__ float4 relu4(float4 a) {
    return make_float4(fmaxf(a.x, 0.f), fmaxf(a.y, 0.f),
                       fmaxf(a.z, 0.f), fmaxf(a.w, 0.f));
}
__device__ __forceinline__ float dot4(float4 a, float4 b) {
    return fmaf(a.x, b.x, fmaf(a.y, b.y, fmaf(a.z, b.z, a.w * b.w)));
}

__device__ __forceinline__ void cp16(float* dst_smem, const float* src) {
    uint32_t d = (uint32_t)__cvta_generic_to_shared(dst_smem);
    asm volatile("cp.async.cg.shared.global [%0], [%1], 16;"
                 :: "r"(d), "l"(src) : "memory");
}

__global__ __launch_bounds__(1024, 1)
void rope_ctx_kernel(const float* __restrict__ q,
                     const float* __restrict__ k,
                     const float* __restrict__ cos_step,
                     const float* __restrict__ sin_step,
                     float* __restrict__ out)
{
    extern __shared__ float smem[];
    float* sk = smem;                      // [2][TILE][64]
    float* sq = smem + 2 * TILE_FLOATS;    // [2][TILE][64]

    __shared__ float2 s_tab[NSTEPS];
    __shared__ float  s_agg[64][33];       // per-dim per-warp tile aggregates
    __shared__ float  s_pref[64][33];      // [d][w+1] inclusive; [d][0] = 0

    const int tid  = threadIdx.x;
    const int w    = tid >> 5;
    const int lane = tid & 31;
    const int g    = lane >> 3;            // row group 0..3
    const int j    = lane & 7;             // dim slot within row
    const int b    = blockIdx.x >> 5;      // H = 32
    const int h    = blockIdx.x & 31;

    if (tid < NSTEPS) {
        s_tab[tid] = make_float2(cos_step[tid * Dv], sin_step[tid * Dv]);
    }
    if (tid < 64) s_pref[tid][0] = 0.f;    // written once, constant thereafter

    const size_t base = (size_t)b * Sv * ROWSTRIDE + (size_t)h * Dv;
    const float* qg = q + base;
    const float* kg = k + base;
    float* og = out + base;
    const size_t KOUT = (size_t)Bv * Sv * ROWSTRIDE;

    const int dx = 4 * j;              // x dims: dx..dx+3 ; y dims: 32+dx..
    const int dy = 32 + 4 * j;
    const int r  = (w << 2) + g;       // this thread's row within a tile
    const int sodx = (r << 6) + dx;
    const int sody = (r << 6) + dy;

    // per-thread-exact staging: this thread copies ONLY the words it reads,
    // so cp.async.wait_group alone (no barrier) makes them visible to it.
    auto issue = [&](int t, int pb) {
        if (t < NTILES) {
            float* skb = sk + pb * TILE_FLOATS;
            float* sqb = sq + pb * TILE_FLOATS;
            const size_t go = (size_t)(t * TILE + r) * ROWSTRIDE;
            cp16(skb + sodx, kg + go + dx);
            cp16(skb + sody, kg + go + dy);
            cp16(sqb + sodx, qg + go + dx);
            cp16(sqb + sody, qg + go + dy);
        }
        asm volatile("cp.async.commit_group;" ::: "memory");
    };

    // carried exclusive cumsum for this lane's 8 dims (replicated across groups)
    float4 basex = make_float4(0.f, 0.f, 0.f, 0.f);
    float4 basey = make_float4(0.f, 0.f, 0.f, 0.f);

    // one full tile: buffers static via compile-time parity p
    auto tile = [&](int t, int p) {
        issue(t + 1, p ^ 1);               // enqueue next BEFORE stalling
        asm volatile("cp.async.wait_group 1;" ::: "memory");  // tile t resident

        const float* skb = sk + p * TILE_FLOATS;
        const float* sqb = sq + p * TILE_FLOATS;
        float4 kx = *(const float4*)(skb + sodx);
        float4 ky = *(const float4*)(skb + sody);
        float4 qx = *(const float4*)(sqb + sodx);
        float4 qy = *(const float4*)(sqb + sody);

        // ---- k: relu, norm (one 3-shfl reduction serves all 4 rows) -------
        float4 knx = relu4(kx), kny = relu4(ky);
        float ss = grp8_sum(dot4(knx, knx) + dot4(kny, kny));
        float kinv = rsqrtf(fmaxf(ss, 1e-24f));   // == 1/(sqrt+1e-6) to ~1e-7
        knx.x *= kinv; knx.y *= kinv; knx.z *= kinv; knx.w *= kinv;
        kny.x *= kinv; kny.y *= kinv; kny.z *= kinv; kny.w *= kinv;

        // ---- in-warp inclusive scan across the 4 rows, per component ------
        float4 ix, iy;
        ix.x = scan_grp(knx.x, lane); ix.y = scan_grp(knx.y, lane);
        ix.z = scan_grp(knx.z, lane); ix.w = scan_grp(knx.w, lane);
        iy.x = scan_grp(kny.x, lane); iy.y = scan_grp(kny.y, lane);
        iy.z = scan_grp(kny.z, lane); iy.w = scan_grp(kny.w, lane);

        // group 3 holds the warp's 4-row totals: publish them
        if (g == 3) {
            s_agg[dx    ][w] = ix.x; s_agg[dx + 1][w] = ix.y;
            s_agg[dx + 2][w] = ix.z; s_agg[dx + 3][w] = ix.w;
            s_agg[dy    ][w] = iy.x; s_agg[dy + 1][w] = iy.y;
            s_agg[dy + 2][w] = iy.z; s_agg[dy + 3][w] = iy.w;
        }

        // ---- q: relu + norm (independent; overlaps barrier arrival) -------
        float4 qrx = relu4(qx), qry = relu4(qy);
        float qs = grp8_sum(dot4(qrx, qrx) + dot4(qry, qry));
        float qinv = rsqrtf(fmaxf(qs, 1e-24f));

        __syncthreads();                   // B1: s_agg ready

        // ---- cross-warp scan phase: warp w scans dims {2w, 2w+1} ----------
        #pragma unroll
        for (int dd = 0; dd < 2; ++dd) {
            const int d = 2 * w + dd;
            float v = s_agg[d][lane];
            float u;
            u = __shfl_up_sync(FULL, v, 1);  if (lane >= 1)  v += u;
            u = __shfl_up_sync(FULL, v, 2);  if (lane >= 2)  v += u;
            u = __shfl_up_sync(FULL, v, 4);  if (lane >= 4)  v += u;
            u = __shfl_up_sync(FULL, v, 8);  if (lane >= 8)  v += u;
            u = __shfl_up_sync(FULL, v, 16); if (lane >= 16) v += u;
            s_pref[d][lane + 1] = v;        // inclusive, shifted by one
        }
        __syncthreads();                   // B2: s_pref ready

        // ---- assemble inclusive cum for this row's dims (branch-free) -----
        float4 cx, cy;
        cx.x = basex.x + s_pref[dx    ][w] + ix.x;
        cx.y = basex.y + s_pref[dx + 1][w] + ix.y;
        cx.z = basex.z + s_pref[dx + 2][w] + ix.z;
        cx.w = basex.w + s_pref[dx + 3][w] + ix.w;
        cy.x = basey.x + s_pref[dy    ][w] + iy.x;
        cy.y = basey.y + s_pref[dy + 1][w] + iy.y;
        cy.z = basey.z + s_pref[dy + 2][w] + iy.z;
        cy.w = basey.w + s_pref[dy + 3][w] + iy.w;

        // advance carried base by the tile grand total
        basex.x += s_pref[dx    ][32]; basex.y += s_pref[dx + 1][32];
        basex.z += s_pref[dx + 2][32]; basex.w += s_pref[dx + 3][32];
        basey.x += s_pref[dy    ][32]; basey.y += s_pref[dy + 1][32];
        basey.z += s_pref[dy + 2][32]; basey.w += s_pref[dy + 3][32];

        // ---- dot, position, rope ------------------------------------------
        float dot = grp8_sum(dot4(qrx, cx) + dot4(qry, cy)) * qinv;

        float pp = fminf(fmaxf(dot * (1.f / 32.f), 0.f), 127.f);
        float pf = floorf(pp);
        int   fi = (int)pf;
        int   ci = (int)ceilf(pp);
        float fr = pp - pf;
        float2 t0 = s_tab[fi], t1 = s_tab[ci];
        float cn = fmaf(fr, t1.x - t0.x, t0.x);
        float sn = fmaf(fr, t1.y - t0.y, t0.y);

        float4 oqx, oqy, okx, oky;
        oqx.x = fmaf(qx.x, cn, -qy.x * sn);  oqy.x = fmaf(qy.x, cn, qx.x * sn);
        oqx.y = fmaf(qx.y, cn, -qy.y * sn);  oqy.y = fmaf(qy.y, cn, qx.y * sn);
        oqx.z = fmaf(qx.z, cn, -qy.z * sn);  oqy.z = fmaf(qy.z, cn, qx.z * sn);
        oqx.w = fmaf(qx.w, cn, -qy.w * sn);  oqy.w = fmaf(qy.w, cn, qx.w * sn);
        okx.x = fmaf(kx.x, cn, -ky.x * sn);  oky.x = fmaf(ky.x, cn, kx.x * sn);
        okx.y = fmaf(kx.y, cn, -ky.y * sn);  oky.y = fmaf(ky.y, cn, kx.y * sn);
        okx.z = fmaf(kx.z, cn, -ky.z * sn);  oky.z = fmaf(ky.z, cn, kx.z * sn);
        okx.w = fmaf(kx.w, cn, -ky.w * sn);  oky.w = fmaf(ky.w, cn, kx.w * sn);

        const size_t ro = (size_t)(t * TILE + r) * ROWSTRIDE + dx;
        __stcs((float4*)(og + ro),             oqx);   // streaming: never re-read
        __stcs((float4*)(og + ro + 32),        oqy);
        __stcs((float4*)(og + KOUT + ro),      okx);
        __stcs((float4*)(og + KOUT + ro + 32), oky);
    };

    // ---- prologue + main loop (parity statically known per call) ----------
    issue(0, 0);
    for (int t = 0; t < NTILES; t += 2) {
        tile(t, 0);
        tile(t + 1, 1);
    }
}

extern "C" void kernel_launch(void* const* d_in, const int* in_sizes, int n_in,
                              void* d_out, int out_size)
{
    const float* q        = (const float*)d_in[0];
    const float* k        = (const float*)d_in[1];
    // d_in[2] = v (unused by the reference math)
    const float* cos_step = (const float*)d_in[3];
    const float* sin_step = (const float*)d_in[4];
    // d_in[5] = offset (unused by the reference math)

    const size_t dyn = (size_t)4 * TILE_FLOATS * sizeof(float);  // 128 KB
    cudaFuncSetAttribute(rope_ctx_kernel,
                         cudaFuncAttributeMaxDynamicSharedMemorySize, (int)dyn);
    rope_ctx_kernel<<<Bv * Hv, 1024, dyn>>>(q, k, cos_step, sin_step,
                                            (float*)d_out);
}

// round 12
// speedup vs baseline: 1.7305x; 1.0230x over previous
#include <cuda_runtime.h>
#include <cstdint>

#define Bv 4
#define Sv 4096
#define Hv 32
#define Dv 64
#define NSTEPS 128
#define ROWSTRIDE (Hv * Dv)       // 2048 floats between consecutive s
#define TILE 64                   // rows per half-tile (4 per warp, 16 warps)
#define NTILES (Sv / TILE)        // 64
#define HTILES (NTILES / 2)       // 32 tiles per half
#define TILE_FLOATS (TILE * Dv)   // 4096 floats = 16 KB
#define FULL 0xffffffffu
#define PADP 33

// sum across the 8 lanes of a row-group (lanes g*8..g*8+7)
__device__ __forceinline__ float grp8_sum(float v) {
    v += __shfl_xor_sync(FULL, v, 4);
    v += __shfl_xor_sync(FULL, v, 2);
    v += __shfl_xor_sync(FULL, v, 1);
    return v;
}
// inclusive scan across the 4 row-groups (stride-8 lanes)
__device__ __forceinline__ float scan_grp(float v, int lane) {
    float t = __shfl_up_sync(FULL, v, 8);
    if (lane >= 8) v += t;
    t = __shfl_up_sync(FULL, v, 16);
    if (lane >= 16) v += t;
    return v;
}
__device__ __forceinline__ float4 relu4(float4 a) {
    return make_float4(fmaxf(a.x, 0.f), fmaxf(a.y, 0.f),
                       fmaxf(a.z, 0.f), fmaxf(a.w, 0.f));
}
__device__ __forceinline__ float dot4(float4 a, float4 b) {
    return fmaf(a.x, b.x, fmaf(a.y, b.y, fmaf(a.z, b.z, a.w * b.w)));
}
__device__ __forceinline__ void cp16(float* dst_smem, const float* src) {
    uint32_t d = (uint32_t)__cvta_generic_to_shared(dst_smem);
    asm volatile("cp.async.cg.shared.global [%0], [%1], 16;"
                 :: "r"(d), "l"(src) : "memory");
}
__device__ __forceinline__ void nbar_sync(int id, int cnt) {
    asm volatile("bar.sync %0, %1;" :: "r"(id), "r"(cnt) : "memory");
}
__device__ __forceinline__ void nbar_arrive(int id, int cnt) {
    asm volatile("bar.arrive %0, %1;" :: "r"(id), "r"(cnt) : "memory");
}

__global__ __launch_bounds__(1024, 1)
void rope_ctx_kernel(const float* __restrict__ q,
                     const float* __restrict__ k,
                     const float* __restrict__ cos_step,
                     const float* __restrict__ sin_step,
                     float* __restrict__ out)
{
    extern __shared__ float smem[];     // [half][2 buf][TILE][64] for k, then q

    __shared__ float2 s_tab[NSTEPS];
    __shared__ float  s_agg[2][64][17];
    __shared__ float  s_pref[2][64][PADP];  // [d][hw+1] incl; [d][0]=0; tot [16]
    __shared__ __align__(16) float s_hand[2][64];  // base published by half H

    const int tid  = threadIdx.x;
    const int w    = tid >> 5;
    const int lane = tid & 31;
    const int H    = w >> 4;               // half 0: even tiles, 1: odd tiles
    const int hw   = w & 15;               // warp within half
    const int g    = lane >> 3;            // row group 0..3
    const int j    = lane & 7;             // dim slot within row
    const int b    = blockIdx.x >> 5;      // H = 32 heads
    const int h    = blockIdx.x & 31;

    float* skH = smem + (size_t)H * 2 * TILE_FLOATS;
    float* sqH = smem + 4 * TILE_FLOATS + (size_t)H * 2 * TILE_FLOATS;

    if (tid < NSTEPS) {
        s_tab[tid] = make_float2(cos_step[tid * Dv], sin_step[tid * Dv]);
    }
    if ((tid & 511) < 64) s_pref[H][tid & 63][0] = 0.f;   // constant thereafter

    const size_t base = (size_t)b * Sv * ROWSTRIDE + (size_t)h * Dv;
    const float* qg = q + base;
    const float* kg = k + base;
    float* og = out + base;
    const size_t KOUT = (size_t)Bv * Sv * ROWSTRIDE;

    const int dx = 4 * j;
    const int dy = 32 + 4 * j;
    const int r  = (hw << 2) + g;          // row within a 64-row tile
    const int sodx = (r << 6) + dx;
    const int sody = (r << 6) + dy;

    // per-thread-exact staging: a thread copies ONLY the words it will read,
    // so cp.async.wait_group alone (no barrier) makes them visible to it.
    auto issue = [&](int t, int p) {
        if (t < NTILES) {
            float* skb = skH + p * TILE_FLOATS;
            float* sqb = sqH + p * TILE_FLOATS;
            const size_t go = (size_t)(t * TILE + r) * ROWSTRIDE;
            cp16(skb + sodx, kg + go + dx);
            cp16(skb + sody, kg + go + dy);
            cp16(sqb + sodx, qg + go + dx);
            cp16(sqb + sody, qg + go + dy);
        }
        asm volatile("cp.async.commit_group;" ::: "memory");
    };

    int t = H;                              // this half's first tile
    issue(t, 0);
    issue(t + 2, 1);

    const int bar_int  = 1 + H;             // internal half barrier (512)
    const int bar_pub  = 3 + H;             // this half publishes on it
    const int bar_con  = 4 - H;             // this half consumes on it

    for (int i = 0; i < HTILES; ++i, t += 2) {
        const int p = i & 1;
        asm volatile("cp.async.wait_group 1;" ::: "memory");   // tile t resident

        const float* skb = skH + p * TILE_FLOATS;
        const float* sqb = sqH + p * TILE_FLOATS;
        float4 kx = *(const float4*)(skb + sodx);
        float4 ky = *(const float4*)(skb + sody);
        float4 qx = *(const float4*)(sqb + sodx);
        float4 qy = *(const float4*)(sqb + sody);

        issue(t + 4, p);            // refill just-consumed buffer (regs hold data)

        // ---- k: relu + norm -------------------------------------------------
        float4 knx = relu4(kx), kny = relu4(ky);
        float ss = grp8_sum(dot4(knx, knx) + dot4(kny, kny));
        float kinv = rsqrtf(fmaxf(ss, 1e-24f));
        knx.x *= kinv; knx.y *= kinv; knx.z *= kinv; knx.w *= kinv;
        kny.x *= kinv; kny.y *= kinv; kny.z *= kinv; kny.w *= kinv;

        // ---- in-warp inclusive scan across the 4 rows ----------------------
        float4 ix, iy;
        ix.x = scan_grp(knx.x, lane); ix.y = scan_grp(knx.y, lane);
        ix.z = scan_grp(knx.z, lane); ix.w = scan_grp(knx.w, lane);
        iy.x = scan_grp(kny.x, lane); iy.y = scan_grp(kny.y, lane);
        iy.z = scan_grp(kny.z, lane); iy.w = scan_grp(kny.w, lane);

        if (g == 3) {               // group 3 holds the warp's 4-row totals
            s_agg[H][dx    ][hw] = ix.x; s_agg[H][dx + 1][hw] = ix.y;
            s_agg[H][dx + 2][hw] = ix.z; s_agg[H][dx + 3][hw] = ix.w;
            s_agg[H][dy    ][hw] = iy.x; s_agg[H][dy + 1][hw] = iy.y;
            s_agg[H][dy + 2][hw] = iy.z; s_agg[H][dy + 3][hw] = iy.w;
        }

        float4 qrx = relu4(qx), qry = relu4(qy);
        float qs = grp8_sum(dot4(qrx, qrx) + dot4(qry, qry));
        float qinv = rsqrtf(fmaxf(qs, 1e-24f));

        nbar_sync(bar_int, 512);    // B1: s_agg[H] published

        // ---- cross-warp scan: warp hw scans dims 4hw..4hw+3 over 16 entries
        #pragma unroll
        for (int dd = 0; dd < 4; ++dd) {
            const int d = 4 * hw + dd;
            float v = (lane < 16) ? s_agg[H][d][lane] : 0.f;
            float u;
            u = __shfl_up_sync(FULL, v, 1);  if (lane >= 1) v += u;
            u = __shfl_up_sync(FULL, v, 2);  if (lane >= 2) v += u;
            u = __shfl_up_sync(FULL, v, 4);  if (lane >= 4) v += u;
            u = __shfl_up_sync(FULL, v, 8);  if (lane >= 8) v += u;
            if (lane < 16) s_pref[H][d][lane + 1] = v;  // excl at [hw], tot [16]
        }
        nbar_sync(bar_int, 512);    // B2: s_pref[H] ready

        // ---- cross-half handoff --------------------------------------------
        const bool first = (i == 0) && (H == 0);
        float4 basex, basey;
        if (!first) {
            nbar_sync(bar_con, 1024);            // wait other half's publish
            basex = *(const float4*)&s_hand[1 - H][dx];
            basey = *(const float4*)&s_hand[1 - H][dy];
        } else {
            basex = make_float4(0.f, 0.f, 0.f, 0.f);
            basey = make_float4(0.f, 0.f, 0.f, 0.f);
        }
        if (H == 0 || i < HTILES - 1) {          // last B tile has no consumer
            if (hw == 0 && lane < 16) {
                const int d = 4 * lane;
                float4 pb = first ? make_float4(0.f, 0.f, 0.f, 0.f)
                                  : *(const float4*)&s_hand[1 - H][d];
                float4 nb;
                nb.x = pb.x + s_pref[H][d    ][16];
                nb.y = pb.y + s_pref[H][d + 1][16];
                nb.z = pb.z + s_pref[H][d + 2][16];
                nb.w = pb.w + s_pref[H][d + 3][16];
                *(float4*)&s_hand[H][d] = nb;    // base(t+1) for the other half
            }
            if (hw == 0) __threadfence_block();
            nbar_arrive(bar_pub, 1024);          // all 512 of this half arrive
        }

        // ---- epilogue: assemble cum, dot, position, rope, store -------------
        float4 cx, cy;
        cx.x = basex.x + s_pref[H][dx    ][hw] + ix.x;
        cx.y = basex.y + s_pref[H][dx + 1][hw] + ix.y;
        cx.z = basex.z + s_pref[H][dx + 2][hw] + ix.z;
        cx.w = basex.w + s_pref[H][dx + 3][hw] + ix.w;
        cy.x = basey.x + s_pref[H][dy    ][hw] + iy.x;
        cy.y = basey.y + s_pref[H][dy + 1][hw] + iy.y;
        cy.z = basey.z + s_pref[H][dy + 2][hw] + iy.z;
        cy.w = basey.w + s_pref[H][dy + 3][hw] + iy.w;

        float dot = grp8_sum(dot4(qrx, cx) + dot4(qry, cy)) * qinv;

        float pp = fminf(fmaxf(dot * (1.f / 32.f), 0.f), 127.f);
        float pf = floorf(pp);
        int   fi = (int)pf;
        int   ci = (int)ceilf(pp);
        float fr = pp - pf;
        float2 t0 = s_tab[fi], t1 = s_tab[ci];
        float cn = fmaf(fr, t1.x - t0.x, t0.x);
        float sn = fmaf(fr, t1.y - t0.y, t0.y);

        float4 oqx, oqy, okx, oky;
        oqx.x = fmaf(qx.x, cn, -qy.x * sn);  oqy.x = fmaf(qy.x, cn, qx.x * sn);
        oqx.y = fmaf(qx.y, cn, -qy.y * sn);  oqy.y = fmaf(qy.y, cn, qx.y * sn);
        oqx.z = fmaf(qx.z, cn, -qy.z * sn);  oqy.z = fmaf(qy.z, cn, qx.z * sn);
        oqx.w = fmaf(qx.w, cn, -qy.w * sn);  oqy.w = fmaf(qy.w, cn, qx.w * sn);
        okx.x = fmaf(kx.x, cn, -ky.x * sn);  oky.x = fmaf(ky.x, cn, kx.x * sn);
        okx.y = fmaf(kx.y, cn, -ky.y * sn);  oky.y = fmaf(ky.y, cn, kx.y * sn);
        okx.z = fmaf(kx.z, cn, -ky.z * sn);  oky.z = fmaf(ky.z, cn, kx.z * sn);
        okx.w = fmaf(kx.w, cn, -ky.w * sn);  oky.w = fmaf(ky.w, cn, kx.w * sn);

        const size_t ro = (size_t)(t * TILE + r) * ROWSTRIDE + dx;
        __stcs((float4*)(og + ro),             oqx);
        __stcs((float4*)(og + ro + 32),        oqy);
        __stcs((float4*)(og + KOUT + ro),      okx);
        __stcs((float4*)(og + KOUT + ro + 32), oky);
    }
}

extern "C" void kernel_launch(void* const* d_in, const int* in_sizes, int n_in,
                              void* d_out, int out_size)
{
    const float* q        = (const float*)d_in[0];
    const float* k        = (const float*)d_in[1];
    // d_in[2] = v (unused by the reference math)
    const float* cos_step = (const float*)d_in[3];
    const float* sin_step = (const float*)d_in[4];
    // d_in[5] = offset (unused by the reference math)

    const size_t dyn = (size_t)8 * TILE_FLOATS * sizeof(float);  // 128 KB
    cudaFuncSetAttribute(rope_ctx_kernel,
                         cudaFuncAttributeMaxDynamicSharedMemorySize, (int)dyn);
    rope_ctx_kernel<<<Bv * Hv, 1024, dyn>>>(q, k, cos_step, sin_step,
                                            (float*)d_out);
}